// round 5
// baseline (speedup 1.0000x reference)
#include <cuda_runtime.h>

#define BB 128
#define NN 512
#define CF 64
#define ALPHA_ 0.2f
#define WTS_STRIDE 36

typedef unsigned long long u64;

// packed f32x2 helpers (sm_100+; ptxas never emits FFMA2 from C++)
__device__ __forceinline__ void ffma2(u64 &d, u64 a, u64 b) {
    asm("fma.rn.f32x2 %0, %1, %2, %0;" : "+l"(d) : "l"(a), "l"(b));
}
__device__ __forceinline__ u64 bcast2(float w) {
    u64 r; unsigned int u = __float_as_uint(w);
    asm("mov.b64 %0, {%1, %1};" : "=l"(r) : "r"(u));
    return r;
}
__device__ __forceinline__ u64 pack2(float a, float b) {
    u64 r; asm("mov.b64 %0, {%1, %2};" : "=l"(r) : "f"(a), "f"(b));
    return r;
}
__device__ __forceinline__ float2 unpack2(u64 v) {
    float2 r; asm("mov.b64 {%0, %1}, %2;" : "=f"(r.x), "=f"(r.y) : "l"(v));
    return r;
}

// scratch (allocation-free rule: __device__ globals)
__device__ __align__(16) float g_h1[BB * NN * CF];
__device__ __align__(16) float g_diff[BB * NN * CF];
__device__ float g_s1[BB * NN];
__device__ float g_s2[BB * NN];

// ---------------------------------------------------------------------------
// Kernel 1: h0 = x@W0, h1 = x@W1 ; store h1, diff=h0-h1, s1=(h0+h1)@a1, s2=...@a2
// f32x2: pack row pairs, broadcast W. 4 FFMA2 per c per thread.
// ---------------------------------------------------------------------------
__global__ __launch_bounds__(256) void gat_gemm_kernel(
    const float* __restrict__ x, const float* __restrict__ W,
    const float* __restrict__ a)
{
    __shared__ float W0s[CF * CF];
    __shared__ float W1s[CF * CF];
    __shared__ float xs[16 * CF];
    __shared__ float redbuf[16][2][2];

    int t = threadIdx.x;
    for (int idx = t; idx < CF * CF; idx += 256) {
        W0s[idx] = W[idx];
        W1s[idx] = W[CF * CF + idx];
    }
    int f = t & 63;
    int g = t >> 6;           // 0..3, each group handles 4 rows
    float a1f = __ldg(&a[f]);
    float a2f = __ldg(&a[CF + f]);
    __syncthreads();

    int rowBase = blockIdx.x * 64;
    for (int it = 0; it < 4; it++) {
        int r0 = rowBase + it * 16;
        ((float4*)xs)[t] = ((const float4*)(x + (size_t)r0 * CF))[t];
        __syncthreads();

        u64 a0_01 = 0ULL, a0_23 = 0ULL, a1_01 = 0ULL, a1_23 = 0ULL;
        #pragma unroll 4
        for (int c = 0; c < CF; c++) {
            u64 w0p = bcast2(W0s[c * CF + f]);
            u64 w1p = bcast2(W1s[c * CF + f]);
            float x0 = xs[(g * 4 + 0) * CF + c];
            float x1 = xs[(g * 4 + 1) * CF + c];
            float x2 = xs[(g * 4 + 2) * CF + c];
            float x3 = xs[(g * 4 + 3) * CF + c];
            u64 x01 = pack2(x0, x1);
            u64 x23 = pack2(x2, x3);
            ffma2(a0_01, x01, w0p);
            ffma2(a0_23, x23, w0p);
            ffma2(a1_01, x01, w1p);
            ffma2(a1_23, x23, w1p);
        }

        float2 h0a = unpack2(a0_01), h0b = unpack2(a0_23);
        float2 h1a = unpack2(a1_01), h1b = unpack2(a1_23);
        float h0v[4] = {h0a.x, h0a.y, h0b.x, h0b.y};
        float h1v[4] = {h1a.x, h1a.y, h1b.x, h1b.y};

        int lane = t & 31;
        int half = (t >> 5) & 1;
        #pragma unroll
        for (int rr = 0; rr < 4; rr++) {
            int row = r0 + g * 4 + rr;
            g_h1[(size_t)row * CF + f] = h1v[rr];
            g_diff[(size_t)row * CF + f] = h0v[rr] - h1v[rr];
            float hs = h0v[rr] + h1v[rr];
            float p1 = hs * a1f;
            float p2 = hs * a2f;
            #pragma unroll
            for (int o = 16; o; o >>= 1) {
                p1 += __shfl_xor_sync(0xffffffffu, p1, o);
                p2 += __shfl_xor_sync(0xffffffffu, p2, o);
            }
            if (lane == 0) {
                redbuf[g * 4 + rr][half][0] = p1;
                redbuf[g * 4 + rr][half][1] = p2;
            }
        }
        __syncthreads();
        if (t < 16) {
            int row = r0 + t;
            g_s1[row] = redbuf[t][0][0] + redbuf[t][1][0];
            g_s2[row] = redbuf[t][0][1] + redbuf[t][1][1];
        }
        __syncthreads();
    }
}

// ---------------------------------------------------------------------------
// Kernel 2: masked softmax attention + aggregation. 1 CTA per batch.
// 16 phases of 32 i's. Phase A: warp softmax -> wts[j][il] (stride 36).
// Phase B: 4i x 8f x (j/8) per thread, all math as packed f32x2 (16 FFMA2/iter).
// ---------------------------------------------------------------------------
#define SMEM_FLOATS (32768 + NN * WTS_STRIDE + NN + NN + 32 + 32 + 64)
#define SMEM_BYTES (SMEM_FLOATS * 4)

__global__ __launch_bounds__(512) void gat_attn_kernel(
    const int* __restrict__ adj, const float* __restrict__ bias,
    float* __restrict__ out)
{
    extern __shared__ float sm[];
    float4* h1s4 = (float4*)sm;                  // 512*16 float4 (32768 floats)
    float*  wts  = sm + 32768;                    // 512*36
    float*  s2s  = wts + NN * WTS_STRIDE;         // 512
    float*  s1s  = s2s + NN;                      // 512
    float*  sums = s1s + NN;                      // 32
    float*  diagw = sums + 32;                    // 32
    float*  biass = diagw + 32;                   // 64

    int b = blockIdx.x;
    int t = threadIdx.x;

    {
        const float4* src = (const float4*)(g_h1 + (size_t)b * NN * CF);
        #pragma unroll
        for (int k = 0; k < 16; k++) h1s4[t + k * 512] = src[t + k * 512];
    }
    s2s[t] = g_s2[b * NN + t];
    s1s[t] = g_s1[b * NN + t];
    if (t < 64) biass[t] = bias[t];
    __syncthreads();

    int warpId = t >> 5, lane = t & 31;
    int jq  = t >> 6;               // 0..7  (64 j's each)
    int slot = t & 63;
    int fi2 = slot & 7;             // owns float4 chunks fi2 and fi2+8
    int i0  = (slot >> 3) << 2;     // 0,4,...,28

    for (int ph = 0; ph < 16; ph++) {
        int iBase = ph * 32;

        // ---- Phase A: each warp computes softmax weights for 2 i's ----
        #pragma unroll
        for (int r = 0; r < 2; r++) {
            int il = (warpId << 1) | r;
            int i = iBase + il;
            float s1i = s1s[i];
            const int* arow = adj + (size_t)i * NN;
            float v[16];
            float m = -1e30f;
            #pragma unroll
            for (int k = 0; k < 16; k++) {
                int j = lane + (k << 5);
                float tv = s1i + s2s[j];
                tv = tv > 0.f ? tv : ALPHA_ * tv;
                v[k] = (__ldg(arow + j) > 0) ? tv : -1e30f;
                m = fmaxf(m, v[k]);
            }
            #pragma unroll
            for (int o = 16; o; o >>= 1)
                m = fmaxf(m, __shfl_xor_sync(0xffffffffu, m, o));
            float s = 0.f;
            #pragma unroll
            for (int k = 0; k < 16; k++) {
                int j = lane + (k << 5);
                float w = __expf(v[k] - m);
                s += w;
                wts[j * WTS_STRIDE + il] = w;
                if (j == i) diagw[il] = w;
            }
            #pragma unroll
            for (int o = 16; o; o >>= 1)
                s += __shfl_xor_sync(0xffffffffu, s, o);
            if (lane == 0) sums[il] = s;
        }
        __syncthreads();

        // ---- Phase B: acc[4i][4 pairs] over this thread's 64-j slice ----
        u64 acc[4][4];
        #pragma unroll
        for (int r = 0; r < 4; r++)
            #pragma unroll
            for (int p = 0; p < 4; p++) acc[r][p] = 0ULL;

        const float4* hp = h1s4 + (jq * 64) * 16 + fi2;
        const float*  wp = wts + (jq * 64) * WTS_STRIDE + i0;
        #pragma unroll 4
        for (int jj = 0; jj < 64; jj++) {
            float4 wv = *(const float4*)wp;              // w[i0..i0+3]
            ulonglong2 ha = *(const ulonglong2*)(hp);    // feat pairs of chunk fi2
            ulonglong2 hb = *(const ulonglong2*)(hp + 8);// feat pairs of chunk fi2+8
            u64 w0 = bcast2(wv.x);
            u64 w1 = bcast2(wv.y);
            u64 w2 = bcast2(wv.z);
            u64 w3 = bcast2(wv.w);
            ffma2(acc[0][0], w0, ha.x); ffma2(acc[0][1], w0, ha.y);
            ffma2(acc[0][2], w0, hb.x); ffma2(acc[0][3], w0, hb.y);
            ffma2(acc[1][0], w1, ha.x); ffma2(acc[1][1], w1, ha.y);
            ffma2(acc[1][2], w1, hb.x); ffma2(acc[1][3], w1, hb.y);
            ffma2(acc[2][0], w2, ha.x); ffma2(acc[2][1], w2, ha.y);
            ffma2(acc[2][2], w2, hb.x); ffma2(acc[2][3], w2, hb.y);
            ffma2(acc[3][0], w3, ha.x); ffma2(acc[3][1], w3, ha.y);
            ffma2(acc[3][2], w3, hb.x); ffma2(acc[3][3], w3, hb.y);
            hp += 16;
            wp += WTS_STRIDE;
        }
        __syncthreads();   // all reads of wts done

        // partial reduction buffer aliased over wts region (8*32*16 f4 = 64KB)
        ulonglong2* red2 = (ulonglong2*)wts;
        #pragma unroll
        for (int r = 0; r < 4; r++) {
            ulonglong2 va; va.x = acc[r][0]; va.y = acc[r][1];
            ulonglong2 vb; vb.x = acc[r][2]; vb.y = acc[r][3];
            red2[(jq * 32 + i0 + r) * 16 + fi2]     = va;
            red2[(jq * 32 + i0 + r) * 16 + fi2 + 8] = vb;
        }
        __syncthreads();

        // combine 8 partials + diag correction + bias, write out
        {
            float4* red4 = (float4*)wts;
            int il = t >> 4;
            int fc = t & 15;
            float4 tot = red4[il * 16 + fc];
            #pragma unroll
            for (int q = 1; q < 8; q++) {
                float4 p = red4[(q * 32 + il) * 16 + fc];
                tot.x += p.x; tot.y += p.y; tot.z += p.z; tot.w += p.w;
            }
            int i = iBase + il;
            float inv = 1.0f / sums[il];
            float wii = diagw[il];
            float4 df = __ldg((const float4*)g_diff + ((size_t)b * NN + i) * 16 + fc);
            float4 bs = ((const float4*)biass)[fc];
            float4 o;
            o.x = (tot.x + wii * df.x) * inv + bs.x;
            o.y = (tot.y + wii * df.y) * inv + bs.y;
            o.z = (tot.z + wii * df.z) * inv + bs.z;
            o.w = (tot.w + wii * df.w) * inv + bs.w;
            ((float4*)out)[((size_t)b * NN + i) * 16 + fc] = o;
        }
        __syncthreads();   // red region becomes wts again next phase
    }
}

// ---------------------------------------------------------------------------
extern "C" void kernel_launch(void* const* d_in, const int* in_sizes, int n_in,
                              void* d_out, int out_size) {
    const float* x    = (const float*)d_in[0];
    const int*   adj  = (const int*)d_in[1];
    const float* W    = (const float*)d_in[2];
    const float* a    = (const float*)d_in[3];
    const float* bias = (const float*)d_in[4];
    float* out = (float*)d_out;

    cudaFuncSetAttribute(gat_attn_kernel,
                         cudaFuncAttributeMaxDynamicSharedMemorySize, SMEM_BYTES);

    gat_gemm_kernel<<<(BB * NN) / 64, 256>>>(x, W, a);
    gat_attn_kernel<<<BB, 512, SMEM_BYTES>>>(adj, bias, out);
}

// round 6
// speedup vs baseline: 1.0012x; 1.0012x over previous
#include <cuda_runtime.h>

#define BB 128
#define NN 512
#define CF 64
#define ALPHA_ 0.2f
#define WTS_STRIDE 36

typedef unsigned long long u64;

// packed f32x2 helpers (sm_100+; ptxas never emits FFMA2 from C++)
__device__ __forceinline__ void ffma2(u64 &d, u64 a, u64 b) {
    asm("fma.rn.f32x2 %0, %1, %2, %0;" : "+l"(d) : "l"(a), "l"(b));
}
__device__ __forceinline__ u64 bcast2(float w) {
    u64 r; unsigned int u = __float_as_uint(w);
    asm("mov.b64 %0, {%1, %1};" : "=l"(r) : "r"(u));
    return r;
}
__device__ __forceinline__ u64 pack2(float a, float b) {
    u64 r; asm("mov.b64 %0, {%1, %2};" : "=l"(r) : "f"(a), "f"(b));
    return r;
}
__device__ __forceinline__ float2 unpack2(u64 v) {
    float2 r; asm("mov.b64 {%0, %1}, %2;" : "=f"(r.x), "=f"(r.y) : "l"(v));
    return r;
}

// scratch (allocation-free rule: __device__ globals)
__device__ __align__(16) float g_h1[BB * NN * CF];
__device__ __align__(16) float g_diff[BB * NN * CF];
__device__ float g_s1[BB * NN];
__device__ float g_s2[BB * NN];

// ---------------------------------------------------------------------------
// Kernel 1: h0 = x@W0, h1 = x@W1 ; store h1, diff=h0-h1, s1=(h0+h1)@a1, s2=...@a2
// f32x2: pack row pairs, broadcast W. 4 FFMA2 per c per thread.
// ---------------------------------------------------------------------------
__global__ __launch_bounds__(256) void gat_gemm_kernel(
    const float* __restrict__ x, const float* __restrict__ W,
    const float* __restrict__ a)
{
    __shared__ float W0s[CF * CF];
    __shared__ float W1s[CF * CF];
    __shared__ float xs[16 * CF];
    __shared__ float redbuf[16][2][2];

    int t = threadIdx.x;
    for (int idx = t; idx < CF * CF; idx += 256) {
        W0s[idx] = W[idx];
        W1s[idx] = W[CF * CF + idx];
    }
    int f = t & 63;
    int g = t >> 6;           // 0..3, each group handles 4 rows
    float a1f = __ldg(&a[f]);
    float a2f = __ldg(&a[CF + f]);
    __syncthreads();

    int rowBase = blockIdx.x * 64;
    for (int it = 0; it < 4; it++) {
        int r0 = rowBase + it * 16;
        ((float4*)xs)[t] = ((const float4*)(x + (size_t)r0 * CF))[t];
        __syncthreads();

        u64 a0_01 = 0ULL, a0_23 = 0ULL, a1_01 = 0ULL, a1_23 = 0ULL;
        #pragma unroll 4
        for (int c = 0; c < CF; c++) {
            u64 w0p = bcast2(W0s[c * CF + f]);
            u64 w1p = bcast2(W1s[c * CF + f]);
            float x0 = xs[(g * 4 + 0) * CF + c];
            float x1 = xs[(g * 4 + 1) * CF + c];
            float x2 = xs[(g * 4 + 2) * CF + c];
            float x3 = xs[(g * 4 + 3) * CF + c];
            u64 x01 = pack2(x0, x1);
            u64 x23 = pack2(x2, x3);
            ffma2(a0_01, x01, w0p);
            ffma2(a0_23, x23, w0p);
            ffma2(a1_01, x01, w1p);
            ffma2(a1_23, x23, w1p);
        }

        float2 h0a = unpack2(a0_01), h0b = unpack2(a0_23);
        float2 h1a = unpack2(a1_01), h1b = unpack2(a1_23);
        float h0v[4] = {h0a.x, h0a.y, h0b.x, h0b.y};
        float h1v[4] = {h1a.x, h1a.y, h1b.x, h1b.y};

        int lane = t & 31;
        int half = (t >> 5) & 1;
        #pragma unroll
        for (int rr = 0; rr < 4; rr++) {
            int row = r0 + g * 4 + rr;
            g_h1[(size_t)row * CF + f] = h1v[rr];
            g_diff[(size_t)row * CF + f] = h0v[rr] - h1v[rr];
            float hs = h0v[rr] + h1v[rr];
            float p1 = hs * a1f;
            float p2 = hs * a2f;
            #pragma unroll
            for (int o = 16; o; o >>= 1) {
                p1 += __shfl_xor_sync(0xffffffffu, p1, o);
                p2 += __shfl_xor_sync(0xffffffffu, p2, o);
            }
            if (lane == 0) {
                redbuf[g * 4 + rr][half][0] = p1;
                redbuf[g * 4 + rr][half][1] = p2;
            }
        }
        __syncthreads();
        if (t < 16) {
            int row = r0 + t;
            g_s1[row] = redbuf[t][0][0] + redbuf[t][1][0];
            g_s2[row] = redbuf[t][0][1] + redbuf[t][1][1];
        }
        __syncthreads();
    }
}

// ---------------------------------------------------------------------------
// Kernel 2: masked softmax attention + aggregation. 1 CTA per batch.
// 16 phases of 32 i's. Phase A: warp softmax -> wts[j][il] (stride 36).
// Phase B: 4i x 8f x (j/8) per thread, all math as packed f32x2 (16 FFMA2/iter).
// ---------------------------------------------------------------------------
#define SMEM_FLOATS (32768 + NN * WTS_STRIDE + NN + NN + 32 + 32 + 64)
#define SMEM_BYTES (SMEM_FLOATS * 4)

__global__ __launch_bounds__(512) void gat_attn_kernel(
    const int* __restrict__ adj, const float* __restrict__ bias,
    float* __restrict__ out)
{
    extern __shared__ float sm[];
    float4* h1s4 = (float4*)sm;                  // 512*16 float4 (32768 floats)
    float*  wts  = sm + 32768;                    // 512*36
    float*  s2s  = wts + NN * WTS_STRIDE;         // 512
    float*  s1s  = s2s + NN;                      // 512
    float*  sums = s1s + NN;                      // 32
    float*  diagw = sums + 32;                    // 32
    float*  biass = diagw + 32;                   // 64

    int b = blockIdx.x;
    int t = threadIdx.x;

    {
        const float4* src = (const float4*)(g_h1 + (size_t)b * NN * CF);
        #pragma unroll
        for (int k = 0; k < 16; k++) h1s4[t + k * 512] = src[t + k * 512];
    }
    s2s[t] = g_s2[b * NN + t];
    s1s[t] = g_s1[b * NN + t];
    if (t < 64) biass[t] = bias[t];
    __syncthreads();

    int warpId = t >> 5, lane = t & 31;
    int jq  = t >> 6;               // 0..7  (64 j's each)
    int slot = t & 63;
    int fi2 = slot & 7;             // owns float4 chunks fi2 and fi2+8
    int i0  = (slot >> 3) << 2;     // 0,4,...,28

    for (int ph = 0; ph < 16; ph++) {
        int iBase = ph * 32;

        // ---- Phase A: each warp computes softmax weights for 2 i's ----
        #pragma unroll
        for (int r = 0; r < 2; r++) {
            int il = (warpId << 1) | r;
            int i = iBase + il;
            float s1i = s1s[i];
            const int* arow = adj + (size_t)i * NN;
            float v[16];
            float m = -1e30f;
            #pragma unroll
            for (int k = 0; k < 16; k++) {
                int j = lane + (k << 5);
                float tv = s1i + s2s[j];
                tv = tv > 0.f ? tv : ALPHA_ * tv;
                v[k] = (__ldg(arow + j) > 0) ? tv : -1e30f;
                m = fmaxf(m, v[k]);
            }
            #pragma unroll
            for (int o = 16; o; o >>= 1)
                m = fmaxf(m, __shfl_xor_sync(0xffffffffu, m, o));
            float s = 0.f;
            #pragma unroll
            for (int k = 0; k < 16; k++) {
                int j = lane + (k << 5);
                float w = __expf(v[k] - m);
                s += w;
                wts[j * WTS_STRIDE + il] = w;
                if (j == i) diagw[il] = w;
            }
            #pragma unroll
            for (int o = 16; o; o >>= 1)
                s += __shfl_xor_sync(0xffffffffu, s, o);
            if (lane == 0) sums[il] = s;
        }
        __syncthreads();

        // ---- Phase B: acc[4i][4 pairs] over this thread's 64-j slice ----
        u64 acc[4][4];
        #pragma unroll
        for (int r = 0; r < 4; r++)
            #pragma unroll
            for (int p = 0; p < 4; p++) acc[r][p] = 0ULL;

        const float4* hp = h1s4 + (jq * 64) * 16 + fi2;
        const float*  wp = wts + (jq * 64) * WTS_STRIDE + i0;
        #pragma unroll 4
        for (int jj = 0; jj < 64; jj++) {
            float4 wv = *(const float4*)wp;              // w[i0..i0+3]
            ulonglong2 ha = *(const ulonglong2*)(hp);    // feat pairs of chunk fi2
            ulonglong2 hb = *(const ulonglong2*)(hp + 8);// feat pairs of chunk fi2+8
            u64 w0 = bcast2(wv.x);
            u64 w1 = bcast2(wv.y);
            u64 w2 = bcast2(wv.z);
            u64 w3 = bcast2(wv.w);
            ffma2(acc[0][0], w0, ha.x); ffma2(acc[0][1], w0, ha.y);
            ffma2(acc[0][2], w0, hb.x); ffma2(acc[0][3], w0, hb.y);
            ffma2(acc[1][0], w1, ha.x); ffma2(acc[1][1], w1, ha.y);
            ffma2(acc[1][2], w1, hb.x); ffma2(acc[1][3], w1, hb.y);
            ffma2(acc[2][0], w2, ha.x); ffma2(acc[2][1], w2, ha.y);
            ffma2(acc[2][2], w2, hb.x); ffma2(acc[2][3], w2, hb.y);
            ffma2(acc[3][0], w3, ha.x); ffma2(acc[3][1], w3, ha.y);
            ffma2(acc[3][2], w3, hb.x); ffma2(acc[3][3], w3, hb.y);
            hp += 16;
            wp += WTS_STRIDE;
        }
        __syncthreads();   // all reads of wts done

        // partial reduction buffer aliased over wts region (8*32*16 f4 = 64KB)
        ulonglong2* red2 = (ulonglong2*)wts;
        #pragma unroll
        for (int r = 0; r < 4; r++) {
            ulonglong2 va; va.x = acc[r][0]; va.y = acc[r][1];
            ulonglong2 vb; vb.x = acc[r][2]; vb.y = acc[r][3];
            red2[(jq * 32 + i0 + r) * 16 + fi2]     = va;
            red2[(jq * 32 + i0 + r) * 16 + fi2 + 8] = vb;
        }
        __syncthreads();

        // combine 8 partials + diag correction + bias, write out
        {
            float4* red4 = (float4*)wts;
            int il = t >> 4;
            int fc = t & 15;
            float4 tot = red4[il * 16 + fc];
            #pragma unroll
            for (int q = 1; q < 8; q++) {
                float4 p = red4[(q * 32 + il) * 16 + fc];
                tot.x += p.x; tot.y += p.y; tot.z += p.z; tot.w += p.w;
            }
            int i = iBase + il;
            float inv = 1.0f / sums[il];
            float wii = diagw[il];
            float4 df = __ldg((const float4*)g_diff + ((size_t)b * NN + i) * 16 + fc);
            float4 bs = ((const float4*)biass)[fc];
            float4 o;
            o.x = (tot.x + wii * df.x) * inv + bs.x;
            o.y = (tot.y + wii * df.y) * inv + bs.y;
            o.z = (tot.z + wii * df.z) * inv + bs.z;
            o.w = (tot.w + wii * df.w) * inv + bs.w;
            ((float4*)out)[((size_t)b * NN + i) * 16 + fc] = o;
        }
        __syncthreads();   // red region becomes wts again next phase
    }
}

// ---------------------------------------------------------------------------
extern "C" void kernel_launch(void* const* d_in, const int* in_sizes, int n_in,
                              void* d_out, int out_size) {
    const float* x    = (const float*)d_in[0];
    const int*   adj  = (const int*)d_in[1];
    const float* W    = (const float*)d_in[2];
    const float* a    = (const float*)d_in[3];
    const float* bias = (const float*)d_in[4];
    float* out = (float*)d_out;

    cudaFuncSetAttribute(gat_attn_kernel,
                         cudaFuncAttributeMaxDynamicSharedMemorySize, SMEM_BYTES);

    gat_gemm_kernel<<<(BB * NN) / 64, 256>>>(x, W, a);
    gat_attn_kernel<<<BB, 512, SMEM_BYTES>>>(adj, bias, out);
}

// round 8
// speedup vs baseline: 2.1038x; 2.1012x over previous
#include <cuda_runtime.h>
#include <cuda_bf16.h>

#define BB 128
#define NN 512
#define CF 64
#define LOG2E 1.4426950408889634f

typedef unsigned int u32;
typedef unsigned long long u64;

// ---------------- scratch ----------------
__device__ __align__(16) unsigned short g_h1hi[BB * NN * CF];
__device__ __align__(16) unsigned short g_h1lo[BB * NN * CF];
__device__ __align__(16) float g_diff[BB * NN * CF];
__device__ float g_s1[BB * NN];
__device__ float g_s2[BB * NN];
__device__ u32 g_adjb[NN * 16];

// ---------------- helpers ----------------
__device__ __forceinline__ void ffma2(u64 &d, u64 a, u64 b) {
    asm("fma.rn.f32x2 %0, %1, %2, %0;" : "+l"(d) : "l"(a), "l"(b));
}
__device__ __forceinline__ u64 bcast2(float w) {
    u64 r; u32 u = __float_as_uint(w);
    asm("mov.b64 %0, {%1, %1};" : "=l"(r) : "r"(u));
    return r;
}
__device__ __forceinline__ u64 pack2(float a, float b) {
    u64 r; asm("mov.b64 %0, {%1, %2};" : "=l"(r) : "f"(a), "f"(b));
    return r;
}
__device__ __forceinline__ float2 unpack2(u64 v) {
    float2 r; asm("mov.b64 {%0, %1}, %2;" : "=f"(r.x), "=f"(r.y) : "l"(v));
    return r;
}
// packed bf16x2: hi16 = bf16(vh), lo16 = bf16(vl)
__device__ __forceinline__ u32 cvt2(float vh, float vl) {
    u32 r; asm("cvt.rn.bf16x2.f32 %0, %1, %2;" : "=r"(r) : "f"(vh), "f"(vl));
    return r;
}
__device__ __forceinline__ u32 smem_u32(const void* p) {
    u32 a;
    asm("{ .reg .u64 t; cvta.to.shared.u64 t, %1; cvt.u32.u64 %0, t; }"
        : "=r"(a) : "l"(p));
    return a;
}
// w = bit ? exp2(max(v, 0.2v)) : 0   (v pre-scaled by log2 e)
__device__ __forceinline__ float wcalc(float v, u32 bit) {
    float u = fmaxf(v, 0.2f * v);
    u = bit ? u : -1e38f;
    float e; asm("ex2.approx.f32 %0, %1;" : "=f"(e) : "f"(u));
    return e;
}

#define LDSM4T(r0, r1, r2, r3, addr) \
    asm volatile("ldmatrix.sync.aligned.m8n8.x4.trans.shared.b16 {%0,%1,%2,%3}, [%4];" \
        : "=r"(r0), "=r"(r1), "=r"(r2), "=r"(r3) : "r"(addr))

#define MMA_BF16(d, a0, a1, a2, a3, b0, b1) \
    asm volatile("mma.sync.aligned.m16n8k16.row.col.f32.bf16.bf16.f32 " \
        "{%0,%1,%2,%3}, {%4,%5,%6,%7}, {%8,%9}, {%0,%1,%2,%3};" \
        : "+f"((d)[0]), "+f"((d)[1]), "+f"((d)[2]), "+f"((d)[3]) \
        : "r"(a0), "r"(a1), "r"(a2), "r"(a3), "r"(b0), "r"(b1))

// ---------------------------------------------------------------------------
// adj -> bitmask
// ---------------------------------------------------------------------------
__global__ __launch_bounds__(512) void adj_bits_kernel(const int* __restrict__ adj) {
    int row = blockIdx.x;
    int t = threadIdx.x;
    int v = adj[(size_t)row * NN + t];
    u32 m = __ballot_sync(0xffffffffu, v > 0);
    if ((t & 31) == 0) g_adjb[row * 16 + (t >> 5)] = m;
}

// ---------------------------------------------------------------------------
// Kernel 1 (R4 logic; outputs h1 as bf16 hi/lo + diff + s1/s2)
// ---------------------------------------------------------------------------
__global__ __launch_bounds__(256) void gat_gemm_kernel(
    const float* __restrict__ x, const float* __restrict__ W,
    const float* __restrict__ a)
{
    __shared__ float W0s[CF * CF];
    __shared__ float W1s[CF * CF];
    __shared__ float xs[16 * CF];
    __shared__ float redbuf[16][2][2];

    int t = threadIdx.x;
    for (int idx = t; idx < CF * CF; idx += 256) {
        W0s[idx] = W[idx];
        W1s[idx] = W[CF * CF + idx];
    }
    int f = t & 63;
    int g = t >> 6;
    float a1f = __ldg(&a[f]);
    float a2f = __ldg(&a[CF + f]);
    __syncthreads();

    int rowBase = blockIdx.x * 64;
    for (int it = 0; it < 4; it++) {
        int r0 = rowBase + it * 16;
        ((float4*)xs)[t] = ((const float4*)(x + (size_t)r0 * CF))[t];
        __syncthreads();

        u64 a0_01 = 0ULL, a0_23 = 0ULL, a1_01 = 0ULL, a1_23 = 0ULL;
        #pragma unroll 4
        for (int c = 0; c < CF; c++) {
            u64 w0p = bcast2(W0s[c * CF + f]);
            u64 w1p = bcast2(W1s[c * CF + f]);
            u64 x01 = pack2(xs[(g * 4 + 0) * CF + c], xs[(g * 4 + 1) * CF + c]);
            u64 x23 = pack2(xs[(g * 4 + 2) * CF + c], xs[(g * 4 + 3) * CF + c]);
            ffma2(a0_01, x01, w0p);
            ffma2(a0_23, x23, w0p);
            ffma2(a1_01, x01, w1p);
            ffma2(a1_23, x23, w1p);
        }
        float2 h0a = unpack2(a0_01), h0b = unpack2(a0_23);
        float2 h1a = unpack2(a1_01), h1b = unpack2(a1_23);
        float h0v[4] = {h0a.x, h0a.y, h0b.x, h0b.y};
        float h1v[4] = {h1a.x, h1a.y, h1b.x, h1b.y};

        int lane = t & 31;
        int half = (t >> 5) & 1;
        #pragma unroll
        for (int rr = 0; rr < 4; rr++) {
            int row = r0 + g * 4 + rr;
            __nv_bfloat16 hb = __float2bfloat16(h1v[rr]);
            float hf = __bfloat162float(hb);
            __nv_bfloat16 lb = __float2bfloat16(h1v[rr] - hf);
            g_h1hi[(size_t)row * CF + f] = *(unsigned short*)&hb;
            g_h1lo[(size_t)row * CF + f] = *(unsigned short*)&lb;
            g_diff[(size_t)row * CF + f] = h0v[rr] - h1v[rr];
            float hs = h0v[rr] + h1v[rr];
            float p1 = hs * a1f, p2 = hs * a2f;
            #pragma unroll
            for (int o = 16; o; o >>= 1) {
                p1 += __shfl_xor_sync(0xffffffffu, p1, o);
                p2 += __shfl_xor_sync(0xffffffffu, p2, o);
            }
            if (lane == 0) {
                redbuf[g * 4 + rr][half][0] = p1;
                redbuf[g * 4 + rr][half][1] = p2;
            }
        }
        __syncthreads();
        if (t < 16) {
            int row = r0 + t;
            g_s1[row] = redbuf[t][0][0] + redbuf[t][1][0];
            g_s2[row] = redbuf[t][0][1] + redbuf[t][1][1];
        }
        __syncthreads();
    }
}

// ---------------------------------------------------------------------------
// Kernel 2: HMMA attention. 1 CTA/batch, 512 threads (16 warps).
// Each warp: 16 i rows x 64 f, 2 phases (256 i each). No mainloop barriers.
// ---------------------------------------------------------------------------
#define SM_HHI  0
#define SM_HLO  65536
#define SM_ADJ  131072            // 512 rows x 17 u32 (padded) = 34816 B
#define SM_S1   165888
#define SM_S2   167936
#define SM_BIAS 169984
#define SMEM_SZ 170240

__global__ __launch_bounds__(512) void gat_attn_kernel(
    const float* __restrict__ bias, float* __restrict__ out)
{
    extern __shared__ char smc[];
    int b = blockIdx.x;
    int t = threadIdx.x;
    u32 smb = smem_u32(smc);

    // ---- stage smem ----
    {
        const u32* ghi = (const u32*)g_h1hi + (size_t)b * (NN * CF / 2);
        const u32* glo = (const u32*)g_h1lo + (size_t)b * (NN * CF / 2);
        #pragma unroll
        for (int k = 0; k < 32; k++) {
            int m = t + k * 512;
            int j = m >> 5, f2 = m & 31;
            u32 off = (u32)(j * 128 + (((f2 >> 2) ^ (j & 7)) << 4) + ((f2 & 3) << 2));
            *(u32*)(smc + SM_HHI + off) = ghi[m];
            *(u32*)(smc + SM_HLO + off) = glo[m];
        }
        u32* adjs = (u32*)(smc + SM_ADJ);
        #pragma unroll
        for (int k = 0; k < 16; k++) {
            int m = t + k * 512;
            adjs[(m >> 4) * 17 + (m & 15)] = g_adjb[m];
        }
        ((float*)(smc + SM_S1))[t] = g_s1[b * NN + t] * LOG2E;
        ((float*)(smc + SM_S2))[t] = g_s2[b * NN + t] * LOG2E;
        if (t < 64) ((float*)(smc + SM_BIAS))[t] = bias[t];
    }
    __syncthreads();

    float* s1s = (float*)(smc + SM_S1);
    float* s2s = (float*)(smc + SM_S2);
    u32*  adjs = (u32*)(smc + SM_ADJ);
    float* bs  = (float*)(smc + SM_BIAS);

    int lane = t & 31, w = t >> 5;
    int qid = lane & 3, gid = lane >> 2;
    int klane = lane & 15;
    int nhalf = lane >> 4;          // 0 or 1
    int k7 = klane & 7;

    // per-g swizzled B column constants
    u32 hbc[4], lbc[4];
    #pragma unroll
    for (int g = 0; g < 4; g++) {
        u32 csw = (u32)((((g << 1) + nhalf) ^ k7) << 4);
        hbc[g] = smb + SM_HHI + csw;
        lbc[g] = smb + SM_HLO + csw;
    }

    #pragma unroll 1
    for (int ph = 0; ph < 2; ph++) {
        int rbase = ph * 256 + w * 16;
        int r = rbase + gid, r2 = r + 8;
        float s1r = s1s[r], s1r2 = s1s[r2];

        float d[8][4];
        #pragma unroll
        for (int i = 0; i < 8; i++)
            #pragma unroll
            for (int k = 0; k < 4; k++) d[i][k] = 0.f;
        float S1sum = 0.f, S2sum = 0.f;

        #pragma unroll 4
        for (int c = 0; c < 32; c++) {
            int j0 = c << 4;
            float2 p0 = *(const float2*)(s2s + j0 + (qid << 1));
            float2 p1 = *(const float2*)(s2s + j0 + (qid << 1) + 8);
            u32 wr  = adjs[r * 17 + (c >> 1)];
            u32 wr2 = adjs[r2 * 17 + (c >> 1)];
            int sh = ((c & 1) << 4) + (qid << 1);
            u32 br  = wr >> sh;
            u32 br2 = wr2 >> sh;

            float w00 = wcalc(s1r + p0.x, br & 1);
            float w01 = wcalc(s1r + p0.y, (br >> 1) & 1);
            float w08 = wcalc(s1r + p1.x, (br >> 8) & 1);
            float w09 = wcalc(s1r + p1.y, (br >> 9) & 1);
            float w10 = wcalc(s1r2 + p0.x, br2 & 1);
            float w11 = wcalc(s1r2 + p0.y, (br2 >> 1) & 1);
            float w18 = wcalc(s1r2 + p1.x, (br2 >> 8) & 1);
            float w19 = wcalc(s1r2 + p1.y, (br2 >> 9) & 1);

            S1sum += (w00 + w01) + (w08 + w09);
            S2sum += (w10 + w11) + (w18 + w19);

            u32 a0 = cvt2(w01, w00);
            u32 a1 = cvt2(w11, w10);
            u32 a2 = cvt2(w09, w08);
            u32 a3 = cvt2(w19, w18);
            u32 l0 = cvt2(w01 - __uint_as_float(a0 & 0xFFFF0000u),
                          w00 - __uint_as_float(a0 << 16));
            u32 l1 = cvt2(w11 - __uint_as_float(a1 & 0xFFFF0000u),
                          w10 - __uint_as_float(a1 << 16));
            u32 l2 = cvt2(w09 - __uint_as_float(a2 & 0xFFFF0000u),
                          w08 - __uint_as_float(a2 << 16));
            u32 l3 = cvt2(w19 - __uint_as_float(a3 & 0xFFFF0000u),
                          w18 - __uint_as_float(a3 << 16));

            u32 kb = (u32)((j0 + klane) << 7);
            #pragma unroll
            for (int g = 0; g < 4; g++) {
                u32 bh0, bh1, bh2, bh3, bl0, bl1, bl2, bl3;
                LDSM4T(bh0, bh1, bh2, bh3, hbc[g] + kb);
                LDSM4T(bl0, bl1, bl2, bl3, lbc[g] + kb);
                MMA_BF16(d[g * 2],     a0, a1, a2, a3, bh0, bh1);
                MMA_BF16(d[g * 2],     a0, a1, a2, a3, bl0, bl1);
                MMA_BF16(d[g * 2],     l0, l1, l2, l3, bh0, bh1);
                MMA_BF16(d[g * 2 + 1], a0, a1, a2, a3, bh2, bh3);
                MMA_BF16(d[g * 2 + 1], a0, a1, a2, a3, bl2, bl3);
                MMA_BF16(d[g * 2 + 1], l0, l1, l2, l3, bh2, bh3);
            }
        }

        // full row sums (butterfly over lane&3 group)
        S1sum += __shfl_xor_sync(0xffffffffu, S1sum, 1);
        S1sum += __shfl_xor_sync(0xffffffffu, S1sum, 2);
        S2sum += __shfl_xor_sync(0xffffffffu, S2sum, 1);
        S2sum += __shfl_xor_sync(0xffffffffu, S2sum, 2);

        // diagonal weights (recomputed directly)
        float dw1 = wcalc(s1r + s2s[r],  (adjs[r * 17 + (r >> 5)] >> (r & 31)) & 1);
        float dw2 = wcalc(s1r2 + s2s[r2], (adjs[r2 * 17 + (r2 >> 5)] >> (r2 & 31)) & 1);

        float inv1 = __fdividef(1.0f, S1sum);
        float inv2 = __fdividef(1.0f, S2sum);
        float wd1 = dw1 * inv1, wd2 = dw2 * inv2;

        const float* dbase = g_diff + (size_t)b * NN * CF;
        float* obase = out + (size_t)b * NN * CF;
        #pragma unroll
        for (int tI = 0; tI < 8; tI++) {
            int nc = tI * 8 + (qid << 1);
            float2 bv = *(const float2*)(bs + nc);
            float2 df1 = __ldg((const float2*)(dbase + (size_t)r * CF + nc));
            float2 df2 = __ldg((const float2*)(dbase + (size_t)r2 * CF + nc));
            float2 o1, o2;
            o1.x = d[tI][0] * inv1 + wd1 * df1.x + bv.x;
            o1.y = d[tI][1] * inv1 + wd1 * df1.y + bv.y;
            o2.x = d[tI][2] * inv2 + wd2 * df2.x + bv.x;
            o2.y = d[tI][3] * inv2 + wd2 * df2.y + bv.y;
            *(float2*)(obase + (size_t)r * CF + nc) = o1;
            *(float2*)(obase + (size_t)r2 * CF + nc) = o2;
        }
    }
}

// ---------------------------------------------------------------------------
extern "C" void kernel_launch(void* const* d_in, const int* in_sizes, int n_in,
                              void* d_out, int out_size) {
    const float* x    = (const float*)d_in[0];
    const int*   adj  = (const int*)d_in[1];
    const float* W    = (const float*)d_in[2];
    const float* a    = (const float*)d_in[3];
    const float* bias = (const float*)d_in[4];
    float* out = (float*)d_out;

    cudaFuncSetAttribute(gat_attn_kernel,
                         cudaFuncAttributeMaxDynamicSharedMemorySize, SMEM_SZ);

    adj_bits_kernel<<<NN, 512>>>(adj);
    gat_gemm_kernel<<<(BB * NN) / 64, 256>>>(x, W, a);
    gat_attn_kernel<<<BB, 512, SMEM_SZ>>>(bias, out);
}